// round 17
// baseline (speedup 1.0000x reference)
#include <cuda_runtime.h>
#include <math.h>
#include <stdint.h>

#define T_SEQ 4096
#define BATCH 2
#define CDIM  1024
#define HD    256
#define NH    4
#define WIN   512

// ---------------- scratch (static device globals; no allocation) ----------------
__device__ float    g_q [(size_t)BATCH * T_SEQ * CDIM];
__device__ float    g_k [(size_t)BATCH * T_SEQ * HD];
__device__ float    g_v [(size_t)BATCH * T_SEQ * HD];
__device__ float    g_invf[HD / 2];
// packed f16x2 operand buffers
__device__ uint32_t g_xh [(size_t)BATCH * T_SEQ * CDIM / 2];
__device__ uint32_t g_aoh[(size_t)BATCH * T_SEQ * CDIM / 2];
__device__ uint32_t g_wqh[CDIM * CDIM / 2];
__device__ uint32_t g_wkh[HD * CDIM / 2];
__device__ uint32_t g_wvh[HD * CDIM / 2];
__device__ uint32_t g_woh[CDIM * CDIM / 2];
// attention operands (single fp16)
__device__ uint32_t g_qph[(size_t)BATCH * T_SEQ * CDIM / 2];
__device__ uint32_t g_kph[(size_t)BATCH * T_SEQ * HD / 2];
__device__ uint32_t g_vth[(size_t)BATCH * HD * T_SEQ / 2];

// ---------------- common helpers ----------------
__device__ __forceinline__ uint16_t to_f16(float x) {
    uint16_t h;
    asm("cvt.rn.f16.f32 %0, %1;" : "=h"(h) : "f"(x));
    return h;
}
__device__ __forceinline__ uint32_t pack2(uint16_t a, uint16_t b) {
    return (uint32_t)a | ((uint32_t)b << 16);
}
__device__ __forceinline__ uint32_t smem_u32p(const void* p) {
    uint32_t a;
    asm("{ .reg .u64 t; cvta.to.shared.u64 t, %1; cvt.u32.u64 %0, t; }" : "=r"(a) : "l"(p));
    return a;
}

#define MMA_F16(d, a, b) \
    asm volatile("mma.sync.aligned.m16n8k16.row.col.f32.f16.f16.f32 " \
        "{%0,%1,%2,%3}, {%4,%5,%6,%7}, {%8,%9}, {%0,%1,%2,%3};" \
        : "+f"((d)[0]), "+f"((d)[1]), "+f"((d)[2]), "+f"((d)[3]) \
        : "r"((a)[0]), "r"((a)[1]), "r"((a)[2]), "r"((a)[3]), \
          "r"((b)[0]), "r"((b)[1]))

#define LDSM4(r0, r1, r2, r3, a) \
    asm volatile("ldmatrix.sync.aligned.m8n8.x4.shared.b16 {%0,%1,%2,%3}, [%4];" \
        : "=r"(r0), "=r"(r1), "=r"(r2), "=r"(r3) : "r"(a))

__device__ __forceinline__ void cpa16(uint32_t sa, const void* ga) {
    asm volatile("cp.async.cg.shared.global [%0], [%1], 16;" :: "r"(sa), "l"(ga));
}
#define CP_COMMIT() asm volatile("cp.async.commit_group;" ::: "memory")
#define CP_WAIT0()  asm volatile("cp.async.wait_group 0;" ::: "memory")

// ============ fused preprocessing: invf + hi-only f16 packs ============
#define PREP_BLOCKS 5376
__global__ __launch_bounds__(256) void prep_all(
    const float* __restrict__ x,  const float* __restrict__ Wq,
    const float* __restrict__ Wk, const float* __restrict__ Wv,
    const float* __restrict__ Wo,
    uint32_t* __restrict__ xh, uint32_t* __restrict__ wqh,
    uint32_t* __restrict__ wkh, uint32_t* __restrict__ wvh,
    uint32_t* __restrict__ woh)
{
    const int bid = blockIdx.x;
    const int tid = threadIdx.x;
    if (bid == 0 && tid < 128) {
        float e = (float)(2 * tid) * (1.0f / HD);
        g_invf[tid] = (float)pow(1000000.0, -(double)e);
    }
    const float* in; uint32_t* oh; int i;
    if (bid < 4096)      { in = x;  oh = xh;  i = bid * 256 + tid; }
    else if (bid < 4608) { in = Wq; oh = wqh; i = (bid - 4096) * 256 + tid; }
    else if (bid < 4736) { in = Wk; oh = wkh; i = (bid - 4608) * 256 + tid; }
    else if (bid < 4864) { in = Wv; oh = wvh; i = (bid - 4736) * 256 + tid; }
    else                 { in = Wo; oh = woh; i = (bid - 4864) * 256 + tid; }

    float4 a = ((const float4*)in)[2 * i];
    float4 b = ((const float4*)in)[2 * i + 1];
    ((uint4*)oh)[i] = make_uint4(
        pack2(to_f16(a.x), to_f16(a.y)), pack2(to_f16(a.z), to_f16(a.w)),
        pack2(to_f16(b.x), to_f16(b.y)), pack2(to_f16(b.z), to_f16(b.w)));
}

// ===== single-term fp16 GEMM: C = Ah·Bh^T, multi-segment N =====
#define STRP 20
#define PART_U32 (128 * STRP)
#define BUF_U32  (2 * PART_U32)             // Ah, Bh
#define GEMM_SMEM (2 * BUF_U32 * 4)         // 40960 B

__global__ __launch_bounds__(256, 2) void gemm_f16(
    int M, int K, int tiles0, int tiles01,
    const uint32_t* __restrict__ Ah,
    const uint32_t* __restrict__ Bh0, float* __restrict__ C0, int N0,
    const uint32_t* __restrict__ Bh1, float* __restrict__ C1, int N1,
    const uint32_t* __restrict__ Bh2, float* __restrict__ C2, int N2)
{
    extern __shared__ uint32_t s32[];
    const uint32_t sb = smem_u32p(s32);

    const int nt = blockIdx.x;
    const uint32_t* Bh; float* C; int N, ntl;
    if (nt < tiles0)       { Bh = Bh0; C = C0; N = N0; ntl = nt; }
    else if (nt < tiles01) { Bh = Bh1; C = C1; N = N1; ntl = nt - tiles0; }
    else                   { Bh = Bh2; C = C2; N = N2; ntl = nt - tiles01; }

    const int tid    = threadIdx.x;
    const int wid    = tid >> 5;
    const int lane   = tid & 31;
    const int quad   = lane >> 2;
    const int tq     = lane & 3;
    const int warp_m = wid & 3;
    const int warp_n = wid >> 2;
    const int m0 = blockIdx.y << 7;
    const int n0 = ntl << 7;
    const int K2 = K >> 1;

    const int jm   = lane >> 3, jr = lane & 7;
    const int a_ro = (jm & 1) * 8 + jr;
    const int a_ko = (jm >> 1) * 4;
    const int b_go = jm >> 1;
    const int b_ko = (jm & 1) * 4;

    const uint32_t* pAh = Ah + (size_t)m0 * K2;
    const uint32_t* pBh = Bh + (size_t)n0 * K2;

    const int r0_ = tid >> 2;
    const int r1_ = 64 + r0_;
    const int qd  = (tid & 3) * 4;

#define LOADP(it, buf) do { \
    int kp = (it) * 16; \
    uint32_t sbase = sb + (uint32_t)(buf) * BUF_U32 * 4u; \
    cpa16(sbase + (uint32_t)(0*PART_U32 + r0_*STRP + qd)*4u, pAh + (size_t)r0_*K2 + kp + qd); \
    cpa16(sbase + (uint32_t)(0*PART_U32 + r1_*STRP + qd)*4u, pAh + (size_t)r1_*K2 + kp + qd); \
    cpa16(sbase + (uint32_t)(1*PART_U32 + r0_*STRP + qd)*4u, pBh + (size_t)r0_*K2 + kp + qd); \
    cpa16(sbase + (uint32_t)(1*PART_U32 + r1_*STRP + qd)*4u, pBh + (size_t)r1_*K2 + kp + qd); \
    CP_COMMIT(); \
} while (0)

    float acc[2][8][4];
#pragma unroll
    for (int mf = 0; mf < 2; mf++)
#pragma unroll
        for (int nf = 0; nf < 8; nf++)
#pragma unroll
            for (int r = 0; r < 4; r++) acc[mf][nf][r] = 0.f;

    const int NT = K / 32;

    LOADP(0, 0);

    for (int it = 0; it < NT; ++it) {
        CP_WAIT0();
        __syncthreads();
        if (it + 1 < NT) LOADP(it + 1, (it + 1) & 1);

        const uint32_t sA = sb + (uint32_t)(it & 1) * BUF_U32 * 4u;
        const uint32_t sB = sA + (uint32_t)PART_U32 * 4u;

#pragma unroll
        for (int ks = 0; ks < 2; ks++) {
            const int kb = ks * 8;
            uint32_t ah[2][4];
#pragma unroll
            for (int mf = 0; mf < 2; mf++) {
                uint32_t ar = sA + (uint32_t)((warp_m*32 + mf*16 + a_ro) * STRP + kb + a_ko) * 4u;
                LDSM4(ah[mf][0], ah[mf][1], ah[mf][2], ah[mf][3], ar);
            }
#pragma unroll
            for (int g = 0; g < 4; g++) {
                uint32_t br = sB + (uint32_t)((warp_n*64 + (2*g + b_go)*8 + jr) * STRP + kb + b_ko) * 4u;
                uint32_t b0h[2], b1h[2];
                LDSM4(b0h[0], b0h[1], b1h[0], b1h[1], br);
#pragma unroll
                for (int mf = 0; mf < 2; mf++) {
                    MMA_F16(acc[mf][2*g],   ah[mf], b0h);
                    MMA_F16(acc[mf][2*g+1], ah[mf], b1h);
                }
            }
        }
    }

#pragma unroll
    for (int mf = 0; mf < 2; mf++) {
        int row = m0 + warp_m * 32 + mf * 16 + quad;
#pragma unroll
        for (int nf = 0; nf < 8; nf++) {
            int col = n0 + warp_n * 64 + nf * 8 + tq * 2;
            *(float2*)(C + (size_t)row * N + col)       = make_float2(acc[mf][nf][0], acc[mf][nf][1]);
            *(float2*)(C + (size_t)(row + 8) * N + col) = make_float2(acc[mf][nf][2], acc[mf][nf][3]);
        }
    }
#undef LOADP
}

// ==== fused: RMSNorm+RoPE (q,k) AND V-transpose, one launch, block-segmented ====
// blocks [0,5120): norm warps (q then k);  [5120,5376): V transpose, 32-token tiles
#define NORM_BLOCKS 5120
#define NT_BLOCKS   (NORM_BLOCKS + BATCH * (T_SEQ / 32))   // 5376
#define NT_SMEM     (256 * 36 * 4)                         // 36864 B

__global__ __launch_bounds__(256) void norm_trans(
    const float* __restrict__ qin, const float* __restrict__ kin,
    const float* __restrict__ vin,
    const float* __restrict__ qg, const float* __restrict__ kg,
    uint32_t* __restrict__ qo, uint32_t* __restrict__ ko,
    uint32_t* __restrict__ vth)
{
    extern __shared__ float st[];
    const int bid = blockIdx.x;
    const int tid = threadIdx.x;

    if (bid >= NORM_BLOCKS) {
        // ---- V transpose segment: 32 tokens x 256 dims ----
        int bt = bid - NORM_BLOCKS;
        int b  = bt >> 7;                    // 128 tiles per batch
        int t0 = (bt & 127) * 32;
        const float* vb = vin + ((size_t)(b * T_SEQ + t0)) * HD;
#pragma unroll
        for (int i = 0; i < 8; i++) {
            int f = i * 256 + tid;
            int t = f >> 6, d4 = (f & 63) * 4;
            float4 x = *(const float4*)(vb + (size_t)t * HD + d4);
            st[(d4 + 0) * 36 + t] = x.x;
            st[(d4 + 1) * 36 + t] = x.y;
            st[(d4 + 2) * 36 + t] = x.z;
            st[(d4 + 3) * 36 + t] = x.w;
        }
        __syncthreads();
#pragma unroll
        for (int i = 0; i < 16; i++) {
            int idx = i * 256 + tid;
            int d = idx >> 4, p = idx & 15;
            float x0 = st[d * 36 + 2 * p];
            float x1 = st[d * 36 + 2 * p + 1];
            vth[((size_t)(b * HD + d)) * (T_SEQ / 2) + (t0 >> 1) + p] =
                pack2(to_f16(x0), to_f16(x1));
        }
        return;
    }

    // ---- RMSNorm + RoPE segment ----
    const int NQ = BATCH * T_SEQ * NH;
    int gw   = bid * 8 + (tid >> 5);
    int lane = tid & 31;

    const float* in; const float* gamma; uint32_t* outp; int t;
    if (gw < NQ) {
        in = qin + (size_t)gw * HD; gamma = qg; outp = qo + (size_t)gw * (HD / 2);
        t = (gw >> 2) & (T_SEQ - 1);
    } else {
        int r = gw - NQ;
        in = kin + (size_t)r * HD; gamma = kg; outp = ko + (size_t)r * (HD / 2);
        t = r & (T_SEQ - 1);
    }

    float v[8];
    *(float4*)&v[0] = *(const float4*)(in + lane * 8);
    *(float4*)&v[4] = *(const float4*)(in + lane * 8 + 4);

    float ss = 0.f;
#pragma unroll
    for (int i = 0; i < 8; i++) ss += v[i] * v[i];
#pragma unroll
    for (int o = 16; o > 0; o >>= 1) ss += __shfl_xor_sync(0xffffffffu, ss, o);

    float r = rsqrtf(ss * (1.0f / HD) + 1e-6f);

    float g[8];
    *(float4*)&g[0] = *(const float4*)(gamma + lane * 8);
    *(float4*)&g[4] = *(const float4*)(gamma + lane * 8 + 4);

    float invf[4];
    *(float4*)invf = *(const float4*)(g_invf + lane * 4);

    float tf = (float)t;
#pragma unroll
    for (int p = 0; p < 4; p++) {
        float ang = tf * invf[p];
        float c, s;
        sincosf(ang, &s, &c);
        float x0 = v[2 * p]     * r * g[2 * p];
        float x1 = v[2 * p + 1] * r * g[2 * p + 1];
        v[2 * p]     = x0 * c - x1 * s;
        v[2 * p + 1] = x0 * s + x1 * c;
    }

    *(uint4*)(outp + lane * 4) = make_uint4(
        pack2(to_f16(v[0]), to_f16(v[1])), pack2(to_f16(v[2]), to_f16(v[3])),
        pack2(to_f16(v[4]), to_f16(v[5])), pack2(to_f16(v[6]), to_f16(v[7])));
}

// ==== sliding-window flash attention: fp16 single; heavy-first CTA order ====
#define AQ_STR 132
#define AV_STR 36
#define OFF_Q    0
#define OFF_KV   (64 * AQ_STR)
#define OFF_PH   (OFF_KV + 9216)
#define OFF_RED  (OFF_PH + 64 * AV_STR)
#define OFF_RED2 (OFF_RED + 256)
#define OFF_MS   (OFF_RED2 + 256)
#define OFF_LS   (OFF_MS + 64)
#define ATTN_U32 (OFF_LS + 64)
#define ATTN_SMEM (ATTN_U32 * 4)            // ~82 KB -> 2 CTAs/SM

__global__ __launch_bounds__(256, 2) void attn_swa_mma(
    const uint32_t* __restrict__ Qph,
    const uint32_t* __restrict__ Kph,
    const uint32_t* __restrict__ Vth,
    uint32_t* __restrict__ Oh)
{
    extern __shared__ uint32_t s[];
    const uint32_t sb = smem_u32p(s);
    uint32_t* Ph   = s + OFF_PH;
    float* red     = (float*)(s + OFF_RED);
    float* red2    = (float*)(s + OFF_RED2);
    float* m_s     = (float*)(s + OFF_MS);
    float* l_s     = (float*)(s + OFF_LS);

    const int tid  = threadIdx.x;
    const int wid  = tid >> 5, lane = tid & 31, quad = lane >> 2, tq = lane & 3;
    const int wm   = wid & 1, wn = wid >> 1;
    const int jm   = lane >> 3, jr = lane & 7;
    const int a_ro = (jm & 1) * 8 + jr;
    const int a_ko = (jm >> 1) * 4;
    const int b_go = jm >> 1;
    const int b_ko = (jm & 1) * 4;

    // heavy-first ordering: 448 CTAs with qt>=8 first, 64 light CTAs (qt<8) last
    int qt, bh;
    if (blockIdx.x < 448) { qt = 8 + blockIdx.x % 56; bh = blockIdx.x / 56; }
    else                  { int j = blockIdx.x - 448; qt = j & 7; bh = j >> 3; }
    const int h  = bh & 3;
    const int b  = bh >> 2;
    const int q0 = qt << 6;

    const uint32_t* qh_g = Qph + ((size_t)(b * T_SEQ + q0)) * (CDIM / 2) + h * (HD / 2);
    const uint32_t* kh_g = Kph + (size_t)b * T_SEQ * (HD / 2);
    const uint32_t* vh_g = Vth + (size_t)b * HD * (T_SEQ / 2);

    // ---- Q tile ----
#pragma unroll
    for (int i = 0; i < 8; i++) {
        int f = i * 256 + tid, row = f >> 5, c4 = (f & 31) * 4;
        cpa16(sb + (uint32_t)(OFF_Q + row * AQ_STR + c4) * 4u, qh_g + (size_t)row * (CDIM / 2) + c4);
    }
    CP_COMMIT();
    if (tid < 64) { m_s[tid] = -1e30f; l_s[tid] = 0.f; }
    CP_WAIT0();
    __syncthreads();

    float oacc[2][8][4];
#pragma unroll
    for (int mf = 0; mf < 2; mf++)
#pragma unroll
        for (int nf = 0; nf < 8; nf++)
#pragma unroll
            for (int r = 0; r < 4; r++) oacc[mf][nf][r] = 0.f;

    int kt0 = q0 - WIN; if (kt0 < 0) kt0 = 0;

    for (int kt = kt0; kt <= q0; kt += 64) {
        __syncthreads();   // A

        // ---- K tile ----
#pragma unroll
        for (int i = 0; i < 8; i++) {
            int f = i * 256 + tid, row = f >> 5, c4 = (f & 31) * 4;
            cpa16(sb + (uint32_t)(OFF_KV + row * AQ_STR + c4) * 4u, kh_g + (size_t)(kt + row) * (HD / 2) + c4);
        }
        CP_COMMIT();
        CP_WAIT0();
        __syncthreads();   // B

        // ---- S = Qh Kh^T ----
        float sacc[2][2][4];
#pragma unroll
        for (int mf = 0; mf < 2; mf++)
#pragma unroll
            for (int nf = 0; nf < 2; nf++)
#pragma unroll
                for (int r = 0; r < 4; r++) sacc[mf][nf][r] = 0.f;

#pragma unroll
        for (int ks = 0; ks < 16; ks++) {
            const int kb = ks * 8;
            uint32_t ah[2][4];
#pragma unroll
            for (int mf = 0; mf < 2; mf++) {
                uint32_t ar = sb + (uint32_t)(OFF_Q + (wm*32 + mf*16 + a_ro) * AQ_STR + kb + a_ko) * 4u;
                LDSM4(ah[mf][0], ah[mf][1], ah[mf][2], ah[mf][3], ar);
            }
            uint32_t br = sb + (uint32_t)(OFF_KV + (wn*16 + b_go*8 + jr) * AQ_STR + kb + b_ko) * 4u;
            uint32_t b0h[2], b1h[2];
            LDSM4(b0h[0], b0h[1], b1h[0], b1h[1], br);
#pragma unroll
            for (int mf = 0; mf < 2; mf++) {
                MMA_F16(sacc[mf][0], ah[mf], b0h);
                MMA_F16(sacc[mf][1], ah[mf], b1h);
            }
        }

        // ---- mask + scale + row max ----
#pragma unroll
        for (int mf = 0; mf < 2; mf++)
#pragma unroll
            for (int half = 0; half < 2; half++) {
                int rowl = wm * 32 + mf * 16 + quad + half * 8;
                int irow = q0 + rowl;
                float mt = -1e30f;
#pragma unroll
                for (int nf = 0; nf < 2; nf++)
#pragma unroll
                    for (int p = 0; p < 2; p++) {
                        int j = kt + wn * 16 + nf * 8 + tq * 2 + p;
                        bool ok = (j <= irow) && (j >= irow - WIN);
                        float x = ok ? sacc[mf][nf][half * 2 + p] * 0.0625f : -1e30f;
                        sacc[mf][nf][half * 2 + p] = x;
                        mt = fmaxf(mt, x);
                    }
                mt = fmaxf(mt, __shfl_xor_sync(0xffffffffu, mt, 1));
                mt = fmaxf(mt, __shfl_xor_sync(0xffffffffu, mt, 2));
                if (tq == 0) red[wn * 64 + rowl] = mt;
            }
        __syncthreads();   // C

        // ---- V^T tile (overlaps softmax) ----
#pragma unroll
        for (int i = 0; i < 8; i++) {
            int f = i * 256 + tid, d = f >> 3, c4 = (f & 7) * 4;
            cpa16(sb + (uint32_t)(OFF_KV + d * AV_STR + c4) * 4u, vh_g + (size_t)d * (T_SEQ / 2) + (kt >> 1) + c4);
        }
        CP_COMMIT();

        float mn_loc[2][2], corr_loc[2][2];
#pragma unroll
        for (int mf = 0; mf < 2; mf++)
#pragma unroll
            for (int half = 0; half < 2; half++) {
                int rowl = wm * 32 + mf * 16 + quad + half * 8;
                float mt = fmaxf(fmaxf(red[rowl], red[64 + rowl]),
                                 fmaxf(red[128 + rowl], red[192 + rowl]));
                float mo = m_s[rowl];
                float mn = fmaxf(mo, mt);
                mn_loc[mf][half]   = mn;
                corr_loc[mf][half] = __expf(mo - mn);
            }

        // ---- P = exp(S - m) -> single fp16; row sums ----
#pragma unroll
        for (int mf = 0; mf < 2; mf++)
#pragma unroll
            for (int half = 0; half < 2; half++) {
                int rowl = wm * 32 + mf * 16 + quad + half * 8;
                float mn = mn_loc[mf][half];
                float rs = 0.f;
#pragma unroll
                for (int nf = 0; nf < 2; nf++) {
                    float p0 = __expf(sacc[mf][nf][half * 2 + 0] - mn);
                    float p1 = __expf(sacc[mf][nf][half * 2 + 1] - mn);
                    rs += p0 + p1;
                    Ph[rowl * AV_STR + wn * 8 + nf * 4 + tq] = pack2(to_f16(p0), to_f16(p1));
                }
                rs += __shfl_xor_sync(0xffffffffu, rs, 1);
                rs += __shfl_xor_sync(0xffffffffu, rs, 2);
                if (tq == 0) red2[wn * 64 + rowl] = rs;
            }
        __syncthreads();   // E

        if (wid < 2 && tq == 0) {
#pragma unroll
            for (int mf = 0; mf < 2; mf++)
#pragma unroll
                for (int half = 0; half < 2; half++) {
                    int rowl = wid * 32 + mf * 16 + quad + half * 8;
                    l_s[rowl] = l_s[rowl] * corr_loc[mf][half] +
                                red2[rowl] + red2[64 + rowl] + red2[128 + rowl] + red2[192 + rowl];
                    m_s[rowl] = mn_loc[mf][half];
                }
        }
#pragma unroll
        for (int mf = 0; mf < 2; mf++) {
            float c0 = corr_loc[mf][0], c1 = corr_loc[mf][1];
#pragma unroll
            for (int nf = 0; nf < 8; nf++) {
                oacc[mf][nf][0] *= c0; oacc[mf][nf][1] *= c0;
                oacc[mf][nf][2] *= c1; oacc[mf][nf][3] *= c1;
            }
        }
        CP_WAIT0();
        __syncthreads();   // F

        // ---- O += Ph Vh ----
#pragma unroll
        for (int kk = 0; kk < 4; kk++) {
            const int kb = kk * 8;
            uint32_t pah[2][4];
#pragma unroll
            for (int mf = 0; mf < 2; mf++) {
                uint32_t ar = sb + (uint32_t)(OFF_PH + (wm*32 + mf*16 + a_ro) * AV_STR + kb + a_ko) * 4u;
                LDSM4(pah[mf][0], pah[mf][1], pah[mf][2], pah[mf][3], ar);
            }
#pragma unroll
            for (int g = 0; g < 4; g++) {
                uint32_t br = sb + (uint32_t)(OFF_KV + (wn*64 + (2*g + b_go)*8 + jr) * AV_STR + kb + b_ko) * 4u;
                uint32_t v0h[2], v1h[2];
                LDSM4(v0h[0], v0h[1], v1h[0], v1h[1], br);
#pragma unroll
                for (int mf = 0; mf < 2; mf++) {
                    MMA_F16(oacc[mf][2*g],   pah[mf], v0h);
                    MMA_F16(oacc[mf][2*g+1], pah[mf], v1h);
                }
            }
        }
    }

    // ---- epilogue: write ao as single packed fp16 (Wo GEMM operand) ----
#pragma unroll
    for (int mf = 0; mf < 2; mf++) {
        int r0 = wm * 32 + mf * 16 + quad;
        float i0 = 1.f / l_s[r0], i1 = 1.f / l_s[r0 + 8];
        size_t base0 = ((size_t)(b * T_SEQ + q0 + r0)) * (CDIM / 2) + h * (HD / 2);
        size_t base1 = base0 + 8 * (CDIM / 2);
#pragma unroll
        for (int nf = 0; nf < 8; nf++) {
            int cp_ = wn * 32 + nf * 4 + tq;
            Oh[base0 + cp_] = pack2(to_f16(oacc[mf][nf][0] * i0), to_f16(oacc[mf][nf][1] * i0));
            Oh[base1 + cp_] = pack2(to_f16(oacc[mf][nf][2] * i1), to_f16(oacc[mf][nf][3] * i1));
        }
    }
}

// ---------------- launch ----------------
extern "C" void kernel_launch(void* const* d_in, const int* in_sizes, int n_in,
                              void* d_out, int out_size)
{
    const float* x  = (const float*)d_in[0];
    const float* Wq = (const float*)d_in[1];
    const float* Wk = (const float*)d_in[2];
    const float* Wv = (const float*)d_in[3];
    const float* Wo = (const float*)d_in[4];
    const float* qg = (const float*)d_in[5];
    const float* kg = (const float*)d_in[6];
    float* out = (float*)d_out;

    float *q, *k, *v;
    uint32_t *xh, *aoh, *wqh, *wkh, *wvh, *woh;
    uint32_t *qph, *kph, *vth;
    cudaGetSymbolAddress((void**)&q,   g_q);
    cudaGetSymbolAddress((void**)&k,   g_k);
    cudaGetSymbolAddress((void**)&v,   g_v);
    cudaGetSymbolAddress((void**)&xh,  g_xh);
    cudaGetSymbolAddress((void**)&aoh, g_aoh);
    cudaGetSymbolAddress((void**)&wqh, g_wqh);
    cudaGetSymbolAddress((void**)&wkh, g_wkh);
    cudaGetSymbolAddress((void**)&wvh, g_wvh);
    cudaGetSymbolAddress((void**)&woh, g_woh);
    cudaGetSymbolAddress((void**)&qph, g_qph);
    cudaGetSymbolAddress((void**)&kph, g_kph);
    cudaGetSymbolAddress((void**)&vth, g_vth);

    const int M = BATCH * T_SEQ;   // 8192

    prep_all<<<PREP_BLOCKS, 256>>>(x, Wq, Wk, Wv, Wo, xh, wqh, wkh, wvh, woh);

    cudaFuncSetAttribute(gemm_f16, cudaFuncAttributeMaxDynamicSharedMemorySize, GEMM_SMEM);

    // fused Q+K+V projection
    gemm_f16<<<dim3(12, M / 128), 256, GEMM_SMEM>>>(
        M, CDIM, 8, 10, xh,
        wqh, q, CDIM,
        wkh, k, HD,
        wvh, v, HD);

    // fused rmsnorm+rope (q,k) + V transpose, one launch
    cudaFuncSetAttribute(norm_trans, cudaFuncAttributeMaxDynamicSharedMemorySize, NT_SMEM);
    norm_trans<<<NT_BLOCKS, 256, NT_SMEM>>>(q, k, v, qg, kg, qph, kph, vth);

    cudaFuncSetAttribute(attn_swa_mma, cudaFuncAttributeMaxDynamicSharedMemorySize, ATTN_SMEM);
    attn_swa_mma<<<BATCH * NH * (T_SEQ / 64), 256, ATTN_SMEM>>>(
        qph, kph, vth, aoh);

    // output projection
    gemm_f16<<<dim3(8, M / 128), 256, GEMM_SMEM>>>(
        M, CDIM, 8, 8, aoh,
        woh, out, CDIM,
        woh, out, CDIM,
        woh, out, CDIM);
}